// round 10
// baseline (speedup 1.0000x reference)
#include <cuda_runtime.h>
#include <cstdint>

#define T_STEPS 12
#define BATCH   64
#define NODE    207
#define HID     16
#define HDIM    6624          // NODE*HID*2
#define IN_DIM  16560         // NODE*HID*5
#define X_DIM   3312          // NODE*HID
#define WSTRIDE 6656          // padded row stride (1664 float4)
#define NB      414           // persistent grid (3 CTAs/SM)
#define NCHUNK  1656          // 4-row chunks per step
#define SMEM_BYTES (WSTRIDE * 4)   // 26.6 KB (h staging) -> 3 CTAs/SM

// Scratch (device globals: allocation-free rule)
__device__ float    g_hz[BATCH * HDIM];
__device__ float    g_inpT[IN_DIM * BATCH];
__device__ float    g_pre[BATCH * HDIM];
__device__ float    g_w[(size_t)HDIM * WSTRIDE];      // padded fp32 W_hh (~176 MB)
__device__ unsigned g_sync[2 + T_STEPS * BATCH];      // [0]=bar count, [1]=phase, [2..]=chunk ctrs

// ---------------------------------------------------------------------------
__global__ __launch_bounds__(256) void kH(const float* __restrict__ W)
{
    const int o = blockIdx.x;
    for (int i = threadIdx.x; i < WSTRIDE; i += 256)
        g_w[(size_t)o * WSTRIDE + i] = (i < HDIM) ? W[(size_t)o * HDIM + i] : 0.f;
}

// ---------------------------------------------------------------------------
// Kernel A: build inpT[:, b] directly (transposed layout).
// ---------------------------------------------------------------------------
__global__ __launch_bounds__(256) void kA(
    const float* __restrict__ hz, const float* __restrict__ sv_t,
    const float* __restrict__ Wf, const float* __restrict__ bf,
    const float* __restrict__ Wg, const float* __restrict__ bg,
    const float* __restrict__ conv_w, float* __restrict__ inpT)
{
    const int blk = blockIdx.x;
    const int b = blk / NODE;
    const int n = blk % NODE;
    const int tid = threadIdx.x;

    __shared__ float sh[HID], sz[HID], sf[HID * 2], sg[HID * HID];

    if (tid < 32) {
        float v = hz[b * HDIM + n * 32 + tid];
        if (tid & 1) sz[tid >> 1] = v;
        else         sh[tid >> 1] = v;
    }
    __syncthreads();

    {
        float acc = bg[tid];
#pragma unroll
        for (int l = 0; l < HID; l++) acc += sz[l] * Wg[l * 256 + tid];
        sg[tid] = tanhf(acc);
    }
    if (tid < 32) {
        float acc = bf[tid];
#pragma unroll
        for (int i = 0; i < HID; i++) acc += sh[i] * Wf[i * 32 + tid];
        sf[tid] = tanhf(acc);
    }
    __syncthreads();

    if (tid < 32) {
        const int i = tid >> 1, c = tid & 1;
        float acc = 0.f;
#pragma unroll
        for (int j = 0; j < HID; j++) acc += sg[i * HID + j] * sf[j * 2 + c];
        const int base = X_DIM + n * 64 + i * 4 + c * 2;
        inpT[(size_t)base * BATCH + b]       = sf[i * 2 + c];
        inpT[(size_t)(base + 1) * BATCH + b] = acc;
    }
    if (tid < HID) {
        float v = sv_t[(b * NODE + n) * 2 + 1];
        inpT[(size_t)(tid * NODE + n) * BATCH + b] = conv_w[tid] * v;
    }
}

// ---------------------------------------------------------------------------
// Kernel B: pre = inp @ W_ih^T + b_ih (Wih streamed evict-first)
// ---------------------------------------------------------------------------
__global__ __launch_bounds__(256) void kB(
    const float* __restrict__ inpT, const float* __restrict__ Wih,
    const float* __restrict__ bih, float* __restrict__ pre)
{
    const int tid = threadIdx.x;
    const int b  = tid & 63;
    const int jg = tid >> 6;
    const int o0 = blockIdx.x * 16 + jg * 4;

    const float* w0 = Wih + (size_t)o0 * IN_DIM;

    float acc[4];
#pragma unroll
    for (int k = 0; k < 4; k++) acc[k] = 0.f;

    for (int i = 0; i < IN_DIM; i += 4) {
        const float x0 = inpT[(size_t)(i    ) * BATCH + b];
        const float x1 = inpT[(size_t)(i + 1) * BATCH + b];
        const float x2 = inpT[(size_t)(i + 2) * BATCH + b];
        const float x3 = inpT[(size_t)(i + 3) * BATCH + b];
#pragma unroll
        for (int k = 0; k < 4; k++) {
            const float4 w = __ldcs(reinterpret_cast<const float4*>(
                                        w0 + (size_t)k * IN_DIM + i));
            acc[k] += w.x * x0 + w.y * x1 + w.z * x2 + w.w * x3;
        }
    }
#pragma unroll
    for (int k = 0; k < 4; k++)
        pre[b * HDIM + o0 + k] = acc[k] + bih[o0 + k];
}

// ---------------------------------------------------------------------------
// Kernel C (persistent, fp32 streaming + WARP-LEVEL WORK STEALING):
// 414 blocks x 256 threads, 3 CTAs/SM (24 warps/SM).
// Per step: stage h to smem, then each WARP steals 4-row chunks via a
// per-step atomic counter (1656 chunks). No static assignment -> no
// straggler-max at the per-step grid barrier.
// ---------------------------------------------------------------------------
extern __shared__ float s_dyn[];

__global__ __launch_bounds__(256, 3) void kC_persist(
    const float* __restrict__ W, const float* __restrict__ pre,
    const float* __restrict__ bhh, float* __restrict__ hz, int t)
{
    float* sh = s_dyn;                 // [0, WSTRIDE) floats
    const int tid  = threadIdx.x;
    const int lane = tid & 31;
    const float4* H4 = reinterpret_cast<const float4*>(sh);

    if (tid < WSTRIDE - HDIM) sh[HDIM + tid] = 0.f;   // zero smem h pad

    for (int step = 0; step < BATCH; step++) {
        const int idx = t * BATCH + step;
        const float* pre_b = pre + (size_t)step * HDIM;
        float* hout = hz + (size_t)step * HDIM;

        if (step > 0) {
            __syncthreads();          // WAR: previous step's readers done
            const float* hp = hz + (size_t)(step - 1) * HDIM;
            for (int i = tid; i < HDIM; i += 256) sh[i] = __ldcg(hp + i);
            __syncthreads();

            // warp-level chunk stealing: 4 rows per chunk
            for (;;) {
                int c;
                if (lane == 0) c = (int)atomicAdd(&g_sync[2 + idx], 1u);
                c = __shfl_sync(0xffffffffu, c, 0);
                if (c >= NCHUNK) break;

                const int rbase = c * 4;
                const float4* W0 = reinterpret_cast<const float4*>(W + (size_t)(rbase    ) * WSTRIDE);
                const float4* W1 = reinterpret_cast<const float4*>(W + (size_t)(rbase + 1) * WSTRIDE);
                const float4* W2 = reinterpret_cast<const float4*>(W + (size_t)(rbase + 2) * WSTRIDE);
                const float4* W3 = reinterpret_cast<const float4*>(W + (size_t)(rbase + 3) * WSTRIDE);

                float a0 = 0.f, a1 = 0.f, a2 = 0.f, a3 = 0.f;
#pragma unroll 1
                for (int cc = 0; cc < 52; cc += 2) {
                    const int k0 = cc * 32 + lane, k1 = k0 + 32;
                    const float4 wa0 = W0[k0], wa1 = W0[k1];
                    const float4 wb0 = W1[k0], wb1 = W1[k1];
                    const float4 wc0 = W2[k0], wc1 = W2[k1];
                    const float4 wd0 = W3[k0], wd1 = W3[k1];
                    const float4 h0  = H4[k0], h1  = H4[k1];
                    a0 += wa0.x*h0.x + wa0.y*h0.y + wa0.z*h0.z + wa0.w*h0.w;
                    a1 += wb0.x*h0.x + wb0.y*h0.y + wb0.z*h0.z + wb0.w*h0.w;
                    a2 += wc0.x*h0.x + wc0.y*h0.y + wc0.z*h0.z + wc0.w*h0.w;
                    a3 += wd0.x*h0.x + wd0.y*h0.y + wd0.z*h0.z + wd0.w*h0.w;
                    a0 += wa1.x*h1.x + wa1.y*h1.y + wa1.z*h1.z + wa1.w*h1.w;
                    a1 += wb1.x*h1.x + wb1.y*h1.y + wb1.z*h1.z + wb1.w*h1.w;
                    a2 += wc1.x*h1.x + wc1.y*h1.y + wc1.z*h1.z + wc1.w*h1.w;
                    a3 += wd1.x*h1.x + wd1.y*h1.y + wd1.z*h1.z + wd1.w*h1.w;
                }
#pragma unroll
                for (int s = 16; s; s >>= 1) {
                    a0 += __shfl_xor_sync(0xffffffffu, a0, s);
                    a1 += __shfl_xor_sync(0xffffffffu, a1, s);
                    a2 += __shfl_xor_sync(0xffffffffu, a2, s);
                    a3 += __shfl_xor_sync(0xffffffffu, a3, s);
                }
                if (lane == 0) {
                    __stcg(hout + rbase    , tanhf(a0 + pre_b[rbase    ] + bhh[rbase    ]));
                    __stcg(hout + rbase + 1, tanhf(a1 + pre_b[rbase + 1] + bhh[rbase + 1]));
                    __stcg(hout + rbase + 2, tanhf(a2 + pre_b[rbase + 2] + bhh[rbase + 2]));
                    __stcg(hout + rbase + 3, tanhf(a3 + pre_b[rbase + 3] + bhh[rbase + 3]));
                }
            }
        } else {
            // step 0: h_prev = 0 -> hout = tanh(pre + bhh), split statically
            for (int o = blockIdx.x * 16 + tid / 16; o < HDIM; o += NB * 16)
                ;   // (handled below by strided loop)
            for (int o = blockIdx.x * 256 + tid; o < HDIM; o += NB * 256)
                __stcg(hout + o, tanhf(pre_b[o] + bhh[o]));
        }

        // grid barrier
        __threadfence();
        __syncthreads();
        if (tid == 0) {
            const unsigned k = (unsigned)(t * BATCH + step + 1);
            const unsigned old = atomicAdd(&g_sync[0], 1u);
            if (old == k * NB - 1u) {
                atomicExch(&g_sync[1], k);
            } else {
                volatile unsigned* ph = &g_sync[1];
                while (*ph < k) __nanosleep(64);
            }
        }
        __syncthreads();
    }
}

// ---------------------------------------------------------------------------
extern "C" void kernel_launch(void* const* d_in, const int* in_sizes, int n_in,
                              void* d_out, int out_size)
{
    const float* sv    = (const float*)d_in[0];
    const float* init0 = (const float*)d_in[1];
    const float* Wf    = (const float*)d_in[2];
    const float* bf    = (const float*)d_in[3];
    const float* Wg    = (const float*)d_in[4];
    const float* bg    = (const float*)d_in[5];
    const float* cw    = (const float*)d_in[6];
    const float* Wih   = (const float*)d_in[7];
    const float* bih   = (const float*)d_in[8];
    const float* Whh   = (const float*)d_in[9];
    const float* bhh   = (const float*)d_in[10];

    float *hz, *inpT, *pre, *wpad;
    unsigned* sync;
    cudaGetSymbolAddress((void**)&hz,   g_hz);
    cudaGetSymbolAddress((void**)&inpT, g_inpT);
    cudaGetSymbolAddress((void**)&pre,  g_pre);
    cudaGetSymbolAddress((void**)&wpad, g_w);
    cudaGetSymbolAddress((void**)&sync, g_sync);

    static int smem_set = 0;
    if (!smem_set) {
        cudaFuncSetAttribute(kC_persist,
                             cudaFuncAttributeMaxDynamicSharedMemorySize,
                             SMEM_BYTES);
        smem_set = 1;
    }

    // Launch order: memset, kH, memcpy, kA, kB, kC -> kC is profiled op #5
    cudaMemsetAsync(sync, 0, (2 + T_STEPS * BATCH) * sizeof(unsigned));
    kH<<<HDIM, 256>>>(Whh);
    cudaMemcpyAsync(hz, init0, (size_t)BATCH * HDIM * sizeof(float),
                    cudaMemcpyDeviceToDevice);

    for (int t = 0; t < T_STEPS; t++) {
        kA<<<BATCH * NODE, 256>>>(hz, sv + (size_t)t * BATCH * NODE * 2,
                                  Wf, bf, Wg, bg, cw, inpT);
        kB<<<HDIM / 16, 256>>>(inpT, Wih, bih, pre);
        kC_persist<<<NB, 256, SMEM_BYTES>>>(wpad, pre, bhh, hz, t);
    }

    cudaMemcpyAsync(d_out, hz, (size_t)BATCH * HDIM * sizeof(float),
                    cudaMemcpyDeviceToDevice);
}